// round 1
// baseline (speedup 1.0000x reference)
#include <cuda_runtime.h>
#include <math.h>

// Problem constants
#define B_ 2
#define S_ 2048
#define D_ 2048
#define H_ 16
#define HD_ 128
#define RD_ 64
#define L_ 512
#define QDIM (HD_ + RD_)      // 192
#define KVDIM (2*HD_ + RD_)   // 320
#define MROWS (B_ * S_)       // 4096

// Scratch (device globals; no cudaMalloc allowed)
__device__ float g_ckv[MROWS * L_];              // x @ w_kv_down
__device__ float g_cq [MROWS * L_];              // x @ w_q_down
__device__ float g_kv [MROWS * H_ * KVDIM];      // kv_full
__device__ float g_q  [MROWS * H_ * QDIM];       // q_full
__device__ float g_ctx[MROWS * H_ * HD_];        // attention context

// ----------------------------------------------------------------------------
// Generic fp32 SGEMM: C[M,N] = A[M,K] @ B[K,N], row-major.
// 128x128 block tile, BK=16, 256 threads, 8x8 micro-tile per thread.
// Requires M%128==0, N%128==0, K%16==0 (true for all shapes here).
// ----------------------------------------------------------------------------
__global__ void __launch_bounds__(256) sgemm_kernel(
    const float* __restrict__ A, const float* __restrict__ Bm,
    float* __restrict__ C, int M, int N, int K)
{
    __shared__ float As[16][128];
    __shared__ float Bs[16][128];

    const int tid  = threadIdx.x;
    const int bRow = blockIdx.y * 128;
    const int bCol = blockIdx.x * 128;
    const int ty   = tid >> 4;   // 0..15 (M dir)
    const int tx   = tid & 15;   // 0..15 (N dir)

    float acc[8][8];
#pragma unroll
    for (int i = 0; i < 8; i++)
#pragma unroll
        for (int j = 0; j < 8; j++) acc[i][j] = 0.f;

    for (int kt = 0; kt < K; kt += 16) {
#pragma unroll
        for (int t = 0; t < 2; t++) {
            int idx = t * 256 + tid;
            // A tile: 128 rows x 16 cols -> store transposed As[k][m]
            int r  = idx >> 2;
            int c4 = idx & 3;
            float4 v = *(const float4*)(A + (size_t)(bRow + r) * K + kt + c4 * 4);
            As[c4*4+0][r] = v.x;
            As[c4*4+1][r] = v.y;
            As[c4*4+2][r] = v.z;
            As[c4*4+3][r] = v.w;
            // B tile: 16 rows x 128 cols -> Bs[k][n]
            int rb = idx >> 5;
            int cb = idx & 31;
            float4 w = *(const float4*)(Bm + (size_t)(kt + rb) * N + bCol + cb * 4);
            *(float4*)&Bs[rb][cb*4] = w;
        }
        __syncthreads();

#pragma unroll
        for (int k = 0; k < 16; k++) {
            float ra[8], rb2[8];
#pragma unroll
            for (int i = 0; i < 8; i++) ra[i]  = As[k][ty*8 + i];
#pragma unroll
            for (int j = 0; j < 8; j++) rb2[j] = Bs[k][tx*8 + j];
#pragma unroll
            for (int i = 0; i < 8; i++)
#pragma unroll
                for (int j = 0; j < 8; j++)
                    acc[i][j] += ra[i] * rb2[j];
        }
        __syncthreads();
    }

#pragma unroll
    for (int i = 0; i < 8; i++) {
        size_t crow = (size_t)(bRow + ty*8 + i) * N + bCol + tx*8;
        *(float4*)(C + crow)     = make_float4(acc[i][0], acc[i][1], acc[i][2], acc[i][3]);
        *(float4*)(C + crow + 4) = make_float4(acc[i][4], acc[i][5], acc[i][6], acc[i][7]);
    }
}

// ----------------------------------------------------------------------------
// RoPE (in place) on q_full[..., 128:192] and kv_full[..., 128:192].
// One block per (b,s); 512 threads = 16 heads x 32 rotation pairs.
// Thread owns dims (i, i+32) of one head -> no read/write race.
// ----------------------------------------------------------------------------
__global__ void __launch_bounds__(512) rope_kernel()
{
    const int bs  = blockIdx.x;          // 0..MROWS-1
    const int s   = bs % S_;
    const int tid = threadIdx.x;
    const int h   = tid >> 5;            // 0..15
    const int i   = tid & 31;            // 0..31

    // inv_freq = 10000^{-i/32}
    const float inv_freq = __expf(-(float)i * (9.210340371976184f / 32.0f));
    const float freq = (float)s * inv_freq;
    float c, sn;
    __sincosf(freq, &sn, &c);
    // use precise versions for better match
    c  = cosf(freq);
    sn = sinf(freq);

    {   // q_rope
        size_t base = ((size_t)bs * H_ + h) * QDIM + HD_;
        float x1 = g_q[base + i];
        float x2 = g_q[base + i + 32];
        g_q[base + i]      = x1 * c - x2 * sn;
        g_q[base + i + 32] = x2 * c + x1 * sn;
    }
    {   // k_rope
        size_t base = ((size_t)bs * H_ + h) * KVDIM + HD_;
        float x1 = g_kv[base + i];
        float x2 = g_kv[base + i + 32];
        g_kv[base + i]      = x1 * c - x2 * sn;
        g_kv[base + i + 32] = x2 * c + x1 * sn;
    }
}

// ----------------------------------------------------------------------------
// Causal flash attention (fp32, online softmax).
// Block = (qt, h, b); 32 q-rows per block; K streamed in 32-col tiles.
// 256 threads: score phase = 1 row x 4 cols per thread;
//              PV phase    = 1 row x 16 v-cols per thread.
// ----------------------------------------------------------------------------
#define TQ 32
#define TK 32
#define QPITCH 193
#define VPITCH 132
#define SPITCH 33
#define ATTN_SMEM ((2*TQ*QPITCH + TK*VPITCH + TQ*SPITCH + 96) * (int)sizeof(float))

__global__ void __launch_bounds__(256) attn_kernel()
{
    extern __shared__ float sm[];
    float* sQ   = sm;                       // [32][193]
    float* sK   = sQ + TQ * QPITCH;         // [32][193]
    float* sV   = sK + TK * QPITCH;         // [32][132]
    float* sS   = sV + TK * VPITCH;         // [32][33]
    float* mRow = sS + TQ * SPITCH;         // [32]
    float* lRow = mRow + 32;                // [32]
    float* aRow = lRow + 32;                // [32]

    const int qt  = blockIdx.x;
    const int h   = blockIdx.y;
    const int b   = blockIdx.z;
    const int qs  = qt * TQ;
    const int tid = threadIdx.x;

    // Load Q tile
    for (int idx = tid; idx < TQ * QDIM; idx += 256) {
        int r = idx / QDIM, k = idx % QDIM;
        sQ[r * QPITCH + k] = g_q[((size_t)(b * S_ + qs + r) * H_ + h) * QDIM + k];
    }
    if (tid < 32) { mRow[tid] = -INFINITY; lRow[tid] = 0.f; }

    float acc[16];
#pragma unroll
    for (int i = 0; i < 16; i++) acc[i] = 0.f;

    const int r_acc = tid >> 3;           // 0..31
    const int col0  = (tid & 7) * 16;     // v-col group
    const int sc0   = (tid & 7) * 4;      // score col group

    const float scale = 0.07216878364870323f;  // 1/sqrt(192)

    for (int kt = 0; kt <= qt; kt++) {
        const int ks = kt * TK;
        __syncthreads();  // previous iter done with sK/sV/sS

        for (int idx = tid; idx < TK * QDIM; idx += 256) {
            int c = idx / QDIM, k = idx % QDIM;
            sK[c * QPITCH + k] = g_kv[((size_t)(b * S_ + ks + c) * H_ + h) * KVDIM + k];
        }
        for (int idx = tid; idx < TK * HD_; idx += 256) {
            int c = idx / HD_, j = idx % HD_;
            sV[c * VPITCH + j] = g_kv[((size_t)(b * S_ + ks + c) * H_ + h) * KVDIM + QDIM + j];
        }
        __syncthreads();

        // Scores: thread computes S[r_acc][sc0 .. sc0+3]
        {
            float s0 = 0.f, s1 = 0.f, s2 = 0.f, s3 = 0.f;
            const float* qrow = &sQ[r_acc * QPITCH];
            const float* k0 = &sK[(sc0 + 0) * QPITCH];
            const float* k1 = &sK[(sc0 + 1) * QPITCH];
            const float* k2 = &sK[(sc0 + 2) * QPITCH];
            const float* k3 = &sK[(sc0 + 3) * QPITCH];
#pragma unroll 8
            for (int k = 0; k < QDIM; k++) {
                float q = qrow[k];
                s0 += q * k0[k];
                s1 += q * k1[k];
                s2 += q * k2[k];
                s3 += q * k3[k];
            }
            const bool diag = (kt == qt);
            const int gr = qs + r_acc;
            float* srow = &sS[r_acc * SPITCH + sc0];
            srow[0] = (diag && (ks + sc0 + 0) > gr) ? -1e30f : s0 * scale;
            srow[1] = (diag && (ks + sc0 + 1) > gr) ? -1e30f : s1 * scale;
            srow[2] = (diag && (ks + sc0 + 2) > gr) ? -1e30f : s2 * scale;
            srow[3] = (diag && (ks + sc0 + 3) > gr) ? -1e30f : s3 * scale;
        }
        __syncthreads();

        // Online softmax row update (one thread per row)
        if (tid < 32) {
            const int r = tid;
            float mold = mRow[r];
            float mx = mold;
#pragma unroll
            for (int c = 0; c < TK; c++) mx = fmaxf(mx, sS[r * SPITCH + c]);
            float a = __expf(mold - mx);
            float sum = 0.f;
#pragma unroll
            for (int c = 0; c < TK; c++) {
                float p = __expf(sS[r * SPITCH + c] - mx);
                sS[r * SPITCH + c] = p;
                sum += p;
            }
            lRow[r] = lRow[r] * a + sum;
            mRow[r] = mx;
            aRow[r] = a;
        }
        __syncthreads();

        // acc = acc*alpha + P @ V
        {
            const float a = aRow[r_acc];
#pragma unroll
            for (int i = 0; i < 16; i++) acc[i] *= a;
#pragma unroll 4
            for (int c = 0; c < TK; c++) {
                float p = sS[r_acc * SPITCH + c];
                const float* vr = &sV[c * VPITCH + col0];
#pragma unroll
                for (int i = 0; i < 16; i++) acc[i] += p * vr[i];
            }
        }
    }

    const float invl = 1.0f / lRow[r_acc];
    size_t ob = ((size_t)(b * S_ + qs + r_acc) * H_ + h) * HD_ + col0;
#pragma unroll
    for (int i = 0; i < 16; i++) g_ctx[ob + i] = acc[i] * invl;
}

// ----------------------------------------------------------------------------
// Launch
// Inputs (metadata order): x, mask, w_kv_down, w_kv_up, w_q_down, w_q_up, w_o
// ----------------------------------------------------------------------------
extern "C" void kernel_launch(void* const* d_in, const int* in_sizes, int n_in,
                              void* d_out, int out_size)
{
    (void)in_sizes; (void)n_in; (void)out_size;
    const float* x         = (const float*)d_in[0];
    const float* w_kv_down = (const float*)d_in[2];
    const float* w_kv_up   = (const float*)d_in[3];
    const float* w_q_down  = (const float*)d_in[4];
    const float* w_q_up    = (const float*)d_in[5];
    const float* w_o       = (const float*)d_in[6];
    float* out = (float*)d_out;

    float *ckv, *cq, *kv, *q, *ctx;
    cudaGetSymbolAddress((void**)&ckv, g_ckv);
    cudaGetSymbolAddress((void**)&cq,  g_cq);
    cudaGetSymbolAddress((void**)&kv,  g_kv);
    cudaGetSymbolAddress((void**)&q,   g_q);
    cudaGetSymbolAddress((void**)&ctx, g_ctx);

    cudaFuncSetAttribute(attn_kernel, cudaFuncAttributeMaxDynamicSharedMemorySize, ATTN_SMEM);

    dim3 blk(256);
    // down projections: [4096,2048] @ [2048,512]
    sgemm_kernel<<<dim3(L_/128, MROWS/128), blk>>>(x, w_kv_down, ckv, MROWS, L_, D_);
    sgemm_kernel<<<dim3(L_/128, MROWS/128), blk>>>(x, w_q_down,  cq,  MROWS, L_, D_);
    // up projections
    sgemm_kernel<<<dim3((H_*KVDIM)/128, MROWS/128), blk>>>(ckv, w_kv_up, kv, MROWS, H_*KVDIM, L_);
    sgemm_kernel<<<dim3((H_*QDIM)/128,  MROWS/128), blk>>>(cq,  w_q_up,  q,  MROWS, H_*QDIM,  L_);
    // rope (in place on q_full / kv_full rope sections)
    rope_kernel<<<MROWS, 512>>>();
    // causal attention -> context
    attn_kernel<<<dim3(S_/TQ, H_, B_), 256, ATTN_SMEM>>>();
    // output projection: [4096,2048] @ [2048,2048]
    sgemm_kernel<<<dim3(D_/128, MROWS/128), blk>>>(ctx, w_o, out, MROWS, D_, D_);
}

// round 2
// speedup vs baseline: 2.2864x; 2.2864x over previous
#include <cuda_runtime.h>
#include <math.h>

// Problem constants
#define B_ 2
#define S_ 2048
#define D_ 2048
#define H_ 16
#define HD_ 128
#define RD_ 64
#define L_ 512
#define QDIM (HD_ + RD_)      // 192
#define KVDIM (2*HD_ + RD_)   // 320
#define MROWS (B_ * S_)       // 4096

// Scratch (device globals; no cudaMalloc allowed)
__device__ float g_ckv[MROWS * L_];              // x @ w_kv_down
__device__ float g_cq [MROWS * L_];              // x @ w_q_down
__device__ float g_kv [MROWS * H_ * KVDIM];      // kv_full
__device__ float g_q  [MROWS * H_ * QDIM];       // q_full
__device__ float g_ctx[MROWS * H_ * HD_];        // attention context

// ----------------------------------------------------------------------------
// Generic fp32 SGEMM: C[M,N] = A[M,K] @ B[K,N], row-major.
// 128x128 block tile, BK=16, 256 threads, 8x8 micro-tile per thread.
// ----------------------------------------------------------------------------
__global__ void __launch_bounds__(256) sgemm_kernel(
    const float* __restrict__ A, const float* __restrict__ Bm,
    float* __restrict__ C, int M, int N, int K)
{
    __shared__ float As[16][128];
    __shared__ float Bs[16][128];

    const int tid  = threadIdx.x;
    const int bRow = blockIdx.y * 128;
    const int bCol = blockIdx.x * 128;
    const int ty   = tid >> 4;   // 0..15 (M dir)
    const int tx   = tid & 15;   // 0..15 (N dir)

    float acc[8][8];
#pragma unroll
    for (int i = 0; i < 8; i++)
#pragma unroll
        for (int j = 0; j < 8; j++) acc[i][j] = 0.f;

    for (int kt = 0; kt < K; kt += 16) {
#pragma unroll
        for (int t = 0; t < 2; t++) {
            int idx = t * 256 + tid;
            int r  = idx >> 2;
            int c4 = idx & 3;
            float4 v = *(const float4*)(A + (size_t)(bRow + r) * K + kt + c4 * 4);
            As[c4*4+0][r] = v.x;
            As[c4*4+1][r] = v.y;
            As[c4*4+2][r] = v.z;
            As[c4*4+3][r] = v.w;
            int rb = idx >> 5;
            int cb = idx & 31;
            float4 w = *(const float4*)(Bm + (size_t)(kt + rb) * N + bCol + cb * 4);
            *(float4*)&Bs[rb][cb*4] = w;
        }
        __syncthreads();

#pragma unroll
        for (int k = 0; k < 16; k++) {
            float ra[8], rb2[8];
#pragma unroll
            for (int i = 0; i < 8; i++) ra[i]  = As[k][ty*8 + i];
#pragma unroll
            for (int j = 0; j < 8; j++) rb2[j] = Bs[k][tx*8 + j];
#pragma unroll
            for (int i = 0; i < 8; i++)
#pragma unroll
                for (int j = 0; j < 8; j++)
                    acc[i][j] += ra[i] * rb2[j];
        }
        __syncthreads();
    }

#pragma unroll
    for (int i = 0; i < 8; i++) {
        size_t crow = (size_t)(bRow + ty*8 + i) * N + bCol + tx*8;
        *(float4*)(C + crow)     = make_float4(acc[i][0], acc[i][1], acc[i][2], acc[i][3]);
        *(float4*)(C + crow + 4) = make_float4(acc[i][4], acc[i][5], acc[i][6], acc[i][7]);
    }
}

// ----------------------------------------------------------------------------
// RoPE (in place) on q_full[..., 128:192] and kv_full[..., 128:192].
// ----------------------------------------------------------------------------
__global__ void __launch_bounds__(512) rope_kernel()
{
    const int bs  = blockIdx.x;          // 0..MROWS-1
    const int s   = bs % S_;
    const int tid = threadIdx.x;
    const int h   = tid >> 5;            // 0..15
    const int i   = tid & 31;            // 0..31

    const float inv_freq = __expf(-(float)i * (9.210340371976184f / 32.0f));
    const float freq = (float)s * inv_freq;
    const float c  = cosf(freq);
    const float sn = sinf(freq);

    {   // q_rope
        size_t base = ((size_t)bs * H_ + h) * QDIM + HD_;
        float x1 = g_q[base + i];
        float x2 = g_q[base + i + 32];
        g_q[base + i]      = x1 * c - x2 * sn;
        g_q[base + i + 32] = x2 * c + x1 * sn;
    }
    {   // k_rope
        size_t base = ((size_t)bs * H_ + h) * KVDIM + HD_;
        float x1 = g_kv[base + i];
        float x2 = g_kv[base + i + 32];
        g_kv[base + i]      = x1 * c - x2 * sn;
        g_kv[base + i + 32] = x2 * c + x1 * sn;
    }
}

// ----------------------------------------------------------------------------
// Causal flash attention, fp32, register-tiled like SGEMM.
// 64x64 score tile per block, 256 threads as 16x16, 4x4 score micro-tile.
// Q and K stored TRANSPOSED in smem -> inner loop = 2x LDS.128 per 16 FMA.
// K streamed over head-dim in 32-wide chunks (keeps smem ~110KB -> occ 2).
// ----------------------------------------------------------------------------
#define TQ 64
#define TK 64
#define QP 68        // pitch for sQt/sKt rows (64 tile rows + pad)
#define VP 132
#define SP 68
// floats: sQt 192*68 + sKt 32*68 + sV 64*132 + sS 64*68 + stats 192
#define ATTN_SMEM ((192*QP + 32*QP + TK*VP + TQ*SP + 192) * (int)sizeof(float))

__global__ void __launch_bounds__(256) attn_kernel()
{
    extern __shared__ float sm[];
    float* sQt  = sm;                   // [192][QP]  (Q transposed: [dim][row])
    float* sKt  = sQt + 192 * QP;       // [32][QP]   (K chunk transposed)
    float* sV   = sKt + 32 * QP;        // [64][VP]
    float* sS   = sV  + TK * VP;        // [64][SP]
    float* mRow = sS  + TQ * SP;        // [64]
    float* lRow = mRow + 64;            // [64]
    float* aRow = lRow + 64;            // [64]

    const int qt  = blockIdx.x;
    const int h   = blockIdx.y;
    const int b   = blockIdx.z;
    const int qs  = qt * TQ;
    const int tid = threadIdx.x;
    const int ty  = tid >> 4;           // 0..15 (q-row group)
    const int tx  = tid & 15;           // 0..15 (k-col group)
    const int r0  = ty * 4;             // first of this thread's 4 q-rows

    // Load Q tile transposed: sQt[k][r]
    for (int idx = tid; idx < TQ * QDIM; idx += 256) {
        int r = idx / QDIM, k = idx % QDIM;
        sQt[k * QP + r] = g_q[((size_t)(b * S_ + qs + r) * H_ + h) * QDIM + k];
    }
    if (tid < TQ) { mRow[tid] = -INFINITY; lRow[tid] = 0.f; }

    float acc[4][8];                    // PV accumulator: 4 rows x 8 v-cols
#pragma unroll
    for (int i = 0; i < 4; i++)
#pragma unroll
        for (int j = 0; j < 8; j++) acc[i][j] = 0.f;

    const float scale = 0.07216878364870323f;  // 1/sqrt(192)

    for (int kt = 0; kt <= qt; kt++) {
        const int ks = kt * TK;
        __syncthreads();  // previous iteration done with sS/sV/sKt

        // Load V tile [64][128] (float4)
        for (int idx4 = tid; idx4 < TK * (HD_ / 4); idx4 += 256) {
            int c = idx4 >> 5, j4 = idx4 & 31;
            float4 v = *(const float4*)(g_kv + ((size_t)(b * S_ + ks + c) * H_ + h) * KVDIM + QDIM + j4 * 4);
            *(float4*)&sV[c * VP + j4 * 4] = v;
        }

        // Scores: 64x64 over QDIM=192 in 6 chunks of 32
        float s[4][4];
#pragma unroll
        for (int i = 0; i < 4; i++)
#pragma unroll
            for (int j = 0; j < 4; j++) s[i][j] = 0.f;

        for (int dc = 0; dc < 6; dc++) {
            if (dc > 0) __syncthreads();   // protect sKt overwrite
            // Load K chunk transposed: sKt[d][c] = K[ks+c][dc*32+d]
            {
                int c = tid >> 5;          // 0..7 base of 8 k-rows stride
                int d = tid & 31;
#pragma unroll
                for (int rr = 0; rr < 8; rr++) {
                    int kc = c + rr * 8;
                    sKt[d * QP + kc] = g_kv[((size_t)(b * S_ + ks + kc) * H_ + h) * KVDIM + dc * 32 + d];
                }
            }
            __syncthreads();
#pragma unroll
            for (int k = 0; k < 32; k++) {
                const int kk = dc * 32 + k;
                float4 qa = *(const float4*)&sQt[kk * QP + r0];
                float4 kb = *(const float4*)&sKt[k  * QP + tx * 4];
                float ra[4] = {qa.x, qa.y, qa.z, qa.w};
                float rb[4] = {kb.x, kb.y, kb.z, kb.w};
#pragma unroll
                for (int i = 0; i < 4; i++)
#pragma unroll
                    for (int j = 0; j < 4; j++)
                        s[i][j] += ra[i] * rb[j];
            }
        }

        // Write scaled+masked scores to sS
        {
            const bool diag = (kt == qt);
#pragma unroll
            for (int i = 0; i < 4; i++) {
                const int gr = qs + r0 + i;
                float4 w;
                float* ws = &w.x;
#pragma unroll
                for (int j = 0; j < 4; j++) {
                    int kc = ks + tx * 4 + j;
                    ws[j] = (diag && kc > gr) ? -1e30f : s[i][j] * scale;
                }
                *(float4*)&sS[(r0 + i) * SP + tx * 4] = w;
            }
        }
        __syncthreads();

        // Online softmax row update (one thread per row)
        if (tid < TQ) {
            const int r = tid;
            float mold = mRow[r];
            float mx = mold;
#pragma unroll
            for (int c = 0; c < TK; c++) mx = fmaxf(mx, sS[r * SP + c]);
            float a = __expf(mold - mx);
            float sum = 0.f;
#pragma unroll
            for (int c = 0; c < TK; c++) {
                float p = __expf(sS[r * SP + c] - mx);
                sS[r * SP + c] = p;
                sum += p;
            }
            lRow[r] = lRow[r] * a + sum;
            mRow[r] = mx;
            aRow[r] = a;
        }
        __syncthreads();

        // acc = acc*alpha + P @ V   (4 rows x 8 v-cols per thread)
        {
            float al[4];
#pragma unroll
            for (int i = 0; i < 4; i++) al[i] = aRow[r0 + i];
#pragma unroll
            for (int i = 0; i < 4; i++)
#pragma unroll
                for (int j = 0; j < 8; j++) acc[i][j] *= al[i];

#pragma unroll 4
            for (int c = 0; c < TK; c++) {
                float4 v0 = *(const float4*)&sV[c * VP + tx * 8];
                float4 v1 = *(const float4*)&sV[c * VP + tx * 8 + 4];
                float p[4];
#pragma unroll
                for (int i = 0; i < 4; i++) p[i] = sS[(r0 + i) * SP + c];
#pragma unroll
                for (int i = 0; i < 4; i++) {
                    acc[i][0] += p[i] * v0.x;
                    acc[i][1] += p[i] * v0.y;
                    acc[i][2] += p[i] * v0.z;
                    acc[i][3] += p[i] * v0.w;
                    acc[i][4] += p[i] * v1.x;
                    acc[i][5] += p[i] * v1.y;
                    acc[i][6] += p[i] * v1.z;
                    acc[i][7] += p[i] * v1.w;
                }
            }
        }
    }

    // Final normalize + store
#pragma unroll
    for (int i = 0; i < 4; i++) {
        const float invl = 1.0f / lRow[r0 + i];
        size_t ob = ((size_t)(b * S_ + qs + r0 + i) * H_ + h) * HD_ + tx * 8;
        float4 o0 = make_float4(acc[i][0]*invl, acc[i][1]*invl, acc[i][2]*invl, acc[i][3]*invl);
        float4 o1 = make_float4(acc[i][4]*invl, acc[i][5]*invl, acc[i][6]*invl, acc[i][7]*invl);
        *(float4*)(g_ctx + ob)     = o0;
        *(float4*)(g_ctx + ob + 4) = o1;
    }
}

// ----------------------------------------------------------------------------
// Launch
// Inputs (metadata order): x, mask, w_kv_down, w_kv_up, w_q_down, w_q_up, w_o
// ----------------------------------------------------------------------------
extern "C" void kernel_launch(void* const* d_in, const int* in_sizes, int n_in,
                              void* d_out, int out_size)
{
    (void)in_sizes; (void)n_in; (void)out_size;
    const float* x         = (const float*)d_in[0];
    const float* w_kv_down = (const float*)d_in[2];
    const float* w_kv_up   = (const float*)d_in[3];
    const float* w_q_down  = (const float*)d_in[4];
    const float* w_q_up    = (const float*)d_in[5];
    const float* w_o       = (const float*)d_in[6];
    float* out = (float*)d_out;

    float *ckv, *cq, *kv, *q, *ctx;
    cudaGetSymbolAddress((void**)&ckv, g_ckv);
    cudaGetSymbolAddress((void**)&cq,  g_cq);
    cudaGetSymbolAddress((void**)&kv,  g_kv);
    cudaGetSymbolAddress((void**)&q,   g_q);
    cudaGetSymbolAddress((void**)&ctx, g_ctx);

    cudaFuncSetAttribute(attn_kernel, cudaFuncAttributeMaxDynamicSharedMemorySize, ATTN_SMEM);

    dim3 blk(256);
    sgemm_kernel<<<dim3(L_/128, MROWS/128), blk>>>(x, w_kv_down, ckv, MROWS, L_, D_);
    sgemm_kernel<<<dim3(L_/128, MROWS/128), blk>>>(x, w_q_down,  cq,  MROWS, L_, D_);
    sgemm_kernel<<<dim3((H_*KVDIM)/128, MROWS/128), blk>>>(ckv, w_kv_up, kv, MROWS, H_*KVDIM, L_);
    sgemm_kernel<<<dim3((H_*QDIM)/128,  MROWS/128), blk>>>(cq,  w_q_up,  q,  MROWS, H_*QDIM,  L_);
    rope_kernel<<<MROWS, 512>>>();
    attn_kernel<<<dim3(S_/TQ, H_, B_), 256, ATTN_SMEM>>>();
    sgemm_kernel<<<dim3(D_/128, MROWS/128), blk>>>(ctx, w_o, out, MROWS, D_, D_);
}

// round 3
// speedup vs baseline: 2.6479x; 1.1581x over previous
#include <cuda_runtime.h>
#include <math.h>
#include <mma.h>

using namespace nvcuda;

// Problem constants
#define B_ 2
#define S_ 2048
#define D_ 2048
#define H_ 16
#define HD_ 128
#define RD_ 64
#define L_ 512
#define QDIM (HD_ + RD_)      // 192
#define KVDIM (2*HD_ + RD_)   // 320
#define MROWS (B_ * S_)       // 4096

// Scratch (device globals; no cudaMalloc allowed)
__device__ float g_ckv[MROWS * L_];              // x @ w_kv_down
__device__ float g_cq [MROWS * L_];              // x @ w_q_down
__device__ float g_kv [MROWS * H_ * KVDIM];      // kv_full
__device__ float g_q  [MROWS * H_ * QDIM];       // q_full
__device__ float g_ctx[MROWS * H_ * HD_];        // attention context

// ----------------------------------------------------------------------------
// TF32 tensor-core GEMM: C[M,N] = A[M,K] @ B[K,N], row-major fp32 in/out.
// 128x128 block tile, BK=32, 256 threads = 8 warps in 2x4 grid.
// Warp tile 64x32 = 4x2 wmma m16n16k8 fragments, fp32 accumulate.
// Requires M%128==0, N%128==0, K%32==0 (true for all shapes here).
// ----------------------------------------------------------------------------
#define AP 40     // A smem pitch (32 + 8)
#define BP 136    // B smem pitch (128 + 8)

__global__ void __launch_bounds__(256) tgemm_kernel(
    const float* __restrict__ A, const float* __restrict__ Bm,
    float* __restrict__ C, int M, int N, int K)
{
    __shared__ float As[128 * AP];
    __shared__ float Bs[32 * BP];

    const int tid  = threadIdx.x;
    const int bRow = blockIdx.y * 128;
    const int bCol = blockIdx.x * 128;
    const int w    = tid >> 5;
    const int wm   = w & 1;      // 0..1  -> 64 rows each
    const int wn   = w >> 1;     // 0..3  -> 32 cols each

    wmma::fragment<wmma::accumulator, 16, 16, 8, float> c[4][2];
#pragma unroll
    for (int i = 0; i < 4; i++)
#pragma unroll
        for (int j = 0; j < 2; j++) wmma::fill_fragment(c[i][j], 0.f);

    // gmem load indices
    const int ar  = tid >> 3;          // 0..31 (row base, 4 passes of 32 rows)
    const int ac4 = tid & 7;           // float4 col within 32
    const int br  = tid >> 6;          // 0..3 (row base, 8 passes? no: 4 rows/pass)
    const int bc4 = tid & 63;          // wait recompute below

    for (int kt = 0; kt < K; kt += 32) {
        // A tile: 128 rows x 32 cols
#pragma unroll
        for (int p = 0; p < 4; p++) {
            int r = p * 32 + ar;
            float4 v = *(const float4*)(A + (size_t)(bRow + r) * K + kt + ac4 * 4);
            *(float4*)&As[r * AP + ac4 * 4] = v;
        }
        // B tile: 32 rows x 128 cols (32 float4 per row; 256 thr = 8 rows/pass)
#pragma unroll
        for (int p = 0; p < 4; p++) {
            int r  = p * 8 + (tid >> 5);
            int c4 = tid & 31;
            float4 v = *(const float4*)(Bm + (size_t)(kt + r) * N + bCol + c4 * 4);
            *(float4*)&Bs[r * BP + c4 * 4] = v;
        }
        __syncthreads();

#pragma unroll
        for (int ks = 0; ks < 32; ks += 8) {
            wmma::fragment<wmma::matrix_a, 16, 16, 8, wmma::precision::tf32, wmma::row_major> a[4];
            wmma::fragment<wmma::matrix_b, 16, 16, 8, wmma::precision::tf32, wmma::row_major> b[2];
#pragma unroll
            for (int i = 0; i < 4; i++) {
                wmma::load_matrix_sync(a[i], &As[(wm * 64 + i * 16) * AP + ks], AP);
#pragma unroll
                for (int t = 0; t < a[i].num_elements; t++)
                    a[i].x[t] = wmma::__float_to_tf32(a[i].x[t]);
            }
#pragma unroll
            for (int j = 0; j < 2; j++) {
                wmma::load_matrix_sync(b[j], &Bs[ks * BP + wn * 32 + j * 16], BP);
#pragma unroll
                for (int t = 0; t < b[j].num_elements; t++)
                    b[j].x[t] = wmma::__float_to_tf32(b[j].x[t]);
            }
#pragma unroll
            for (int i = 0; i < 4; i++)
#pragma unroll
                for (int j = 0; j < 2; j++)
                    wmma::mma_sync(c[i][j], a[i], b[j], c[i][j]);
        }
        __syncthreads();
    }

#pragma unroll
    for (int i = 0; i < 4; i++)
#pragma unroll
        for (int j = 0; j < 2; j++) {
            size_t row = bRow + wm * 64 + i * 16;
            size_t col = bCol + wn * 32 + j * 16;
            wmma::store_matrix_sync(C + row * N + col, c[i][j], N, wmma::mem_row_major);
        }
}

// ----------------------------------------------------------------------------
// RoPE (in place) on q_full[..., 128:192] and kv_full[..., 128:192].
// ----------------------------------------------------------------------------
__global__ void __launch_bounds__(512) rope_kernel()
{
    const int bs  = blockIdx.x;          // 0..MROWS-1
    const int s   = bs % S_;
    const int tid = threadIdx.x;
    const int h   = tid >> 5;            // 0..15
    const int i   = tid & 31;            // 0..31

    const float inv_freq = __expf(-(float)i * (9.210340371976184f / 32.0f));
    const float freq = (float)s * inv_freq;
    const float c  = cosf(freq);
    const float sn = sinf(freq);

    {   // q_rope
        size_t base = ((size_t)bs * H_ + h) * QDIM + HD_;
        float x1 = g_q[base + i];
        float x2 = g_q[base + i + 32];
        g_q[base + i]      = x1 * c - x2 * sn;
        g_q[base + i + 32] = x2 * c + x1 * sn;
    }
    {   // k_rope
        size_t base = ((size_t)bs * H_ + h) * KVDIM + HD_;
        float x1 = g_kv[base + i];
        float x2 = g_kv[base + i + 32];
        g_kv[base + i]      = x1 * c - x2 * sn;
        g_kv[base + i + 32] = x2 * c + x1 * sn;
    }
}

// ----------------------------------------------------------------------------
// Causal flash attention, fp32, register-tiled (unchanged from round 2).
// ----------------------------------------------------------------------------
#define TQ 64
#define TK 64
#define QP 68
#define VP 132
#define SP 68
#define ATTN_SMEM ((192*QP + 32*QP + TK*VP + TQ*SP + 192) * (int)sizeof(float))

__global__ void __launch_bounds__(256) attn_kernel()
{
    extern __shared__ float sm[];
    float* sQt  = sm;                   // [192][QP]
    float* sKt  = sQt + 192 * QP;       // [32][QP]
    float* sV   = sKt + 32 * QP;        // [64][VP]
    float* sS   = sV  + TK * VP;        // [64][SP]
    float* mRow = sS  + TQ * SP;        // [64]
    float* lRow = mRow + 64;
    float* aRow = lRow + 64;

    const int qt  = blockIdx.x;
    const int h   = blockIdx.y;
    const int b   = blockIdx.z;
    const int qs  = qt * TQ;
    const int tid = threadIdx.x;
    const int ty  = tid >> 4;
    const int tx  = tid & 15;
    const int r0  = ty * 4;

    for (int idx = tid; idx < TQ * QDIM; idx += 256) {
        int r = idx / QDIM, k = idx % QDIM;
        sQt[k * QP + r] = g_q[((size_t)(b * S_ + qs + r) * H_ + h) * QDIM + k];
    }
    if (tid < TQ) { mRow[tid] = -INFINITY; lRow[tid] = 0.f; }

    float acc[4][8];
#pragma unroll
    for (int i = 0; i < 4; i++)
#pragma unroll
        for (int j = 0; j < 8; j++) acc[i][j] = 0.f;

    const float scale = 0.07216878364870323f;  // 1/sqrt(192)

    for (int kt = 0; kt <= qt; kt++) {
        const int ks = kt * TK;
        __syncthreads();

        for (int idx4 = tid; idx4 < TK * (HD_ / 4); idx4 += 256) {
            int c = idx4 >> 5, j4 = idx4 & 31;
            float4 v = *(const float4*)(g_kv + ((size_t)(b * S_ + ks + c) * H_ + h) * KVDIM + QDIM + j4 * 4);
            *(float4*)&sV[c * VP + j4 * 4] = v;
        }

        float s[4][4];
#pragma unroll
        for (int i = 0; i < 4; i++)
#pragma unroll
            for (int j = 0; j < 4; j++) s[i][j] = 0.f;

        for (int dc = 0; dc < 6; dc++) {
            if (dc > 0) __syncthreads();
            {
                int c = tid >> 5;
                int d = tid & 31;
#pragma unroll
                for (int rr = 0; rr < 8; rr++) {
                    int kc = c + rr * 8;
                    sKt[d * QP + kc] = g_kv[((size_t)(b * S_ + ks + kc) * H_ + h) * KVDIM + dc * 32 + d];
                }
            }
            __syncthreads();
#pragma unroll
            for (int k = 0; k < 32; k++) {
                const int kk = dc * 32 + k;
                float4 qa = *(const float4*)&sQt[kk * QP + r0];
                float4 kb = *(const float4*)&sKt[k  * QP + tx * 4];
                float ra[4] = {qa.x, qa.y, qa.z, qa.w};
                float rb[4] = {kb.x, kb.y, kb.z, kb.w};
#pragma unroll
                for (int i = 0; i < 4; i++)
#pragma unroll
                    for (int j = 0; j < 4; j++)
                        s[i][j] += ra[i] * rb[j];
            }
        }

        {
            const bool diag = (kt == qt);
#pragma unroll
            for (int i = 0; i < 4; i++) {
                const int gr = qs + r0 + i;
                float4 w;
                float* ws = &w.x;
#pragma unroll
                for (int j = 0; j < 4; j++) {
                    int kc = ks + tx * 4 + j;
                    ws[j] = (diag && kc > gr) ? -1e30f : s[i][j] * scale;
                }
                *(float4*)&sS[(r0 + i) * SP + tx * 4] = w;
            }
        }
        __syncthreads();

        if (tid < TQ) {
            const int r = tid;
            float mold = mRow[r];
            float mx = mold;
#pragma unroll
            for (int c = 0; c < TK; c++) mx = fmaxf(mx, sS[r * SP + c]);
            float a = __expf(mold - mx);
            float sum = 0.f;
#pragma unroll
            for (int c = 0; c < TK; c++) {
                float p = __expf(sS[r * SP + c] - mx);
                sS[r * SP + c] = p;
                sum += p;
            }
            lRow[r] = lRow[r] * a + sum;
            mRow[r] = mx;
            aRow[r] = a;
        }
        __syncthreads();

        {
            float al[4];
#pragma unroll
            for (int i = 0; i < 4; i++) al[i] = aRow[r0 + i];
#pragma unroll
            for (int i = 0; i < 4; i++)
#pragma unroll
                for (int j = 0; j < 8; j++) acc[i][j] *= al[i];

#pragma unroll 4
            for (int c = 0; c < TK; c++) {
                float4 v0 = *(const float4*)&sV[c * VP + tx * 8];
                float4 v1 = *(const float4*)&sV[c * VP + tx * 8 + 4];
                float p[4];
#pragma unroll
                for (int i = 0; i < 4; i++) p[i] = sS[(r0 + i) * SP + c];
#pragma unroll
                for (int i = 0; i < 4; i++) {
                    acc[i][0] += p[i] * v0.x;
                    acc[i][1] += p[i] * v0.y;
                    acc[i][2] += p[i] * v0.z;
                    acc[i][3] += p[i] * v0.w;
                    acc[i][4] += p[i] * v1.x;
                    acc[i][5] += p[i] * v1.y;
                    acc[i][6] += p[i] * v1.z;
                    acc[i][7] += p[i] * v1.w;
                }
            }
        }
    }

#pragma unroll
    for (int i = 0; i < 4; i++) {
        const float invl = 1.0f / lRow[r0 + i];
        size_t ob = ((size_t)(b * S_ + qs + r0 + i) * H_ + h) * HD_ + tx * 8;
        float4 o0 = make_float4(acc[i][0]*invl, acc[i][1]*invl, acc[i][2]*invl, acc[i][3]*invl);
        float4 o1 = make_float4(acc[i][4]*invl, acc[i][5]*invl, acc[i][6]*invl, acc[i][7]*invl);
        *(float4*)(g_ctx + ob)     = o0;
        *(float4*)(g_ctx + ob + 4) = o1;
    }
}

// ----------------------------------------------------------------------------
// Launch
// Inputs (metadata order): x, mask, w_kv_down, w_kv_up, w_q_down, w_q_up, w_o
// ----------------------------------------------------------------------------
extern "C" void kernel_launch(void* const* d_in, const int* in_sizes, int n_in,
                              void* d_out, int out_size)
{
    (void)in_sizes; (void)n_in; (void)out_size;
    const float* x         = (const float*)d_in[0];
    const float* w_kv_down = (const float*)d_in[2];
    const float* w_kv_up   = (const float*)d_in[3];
    const float* w_q_down  = (const float*)d_in[4];
    const float* w_q_up    = (const float*)d_in[5];
    const float* w_o       = (const float*)d_in[6];
    float* out = (float*)d_out;

    float *ckv, *cq, *kv, *q, *ctx;
    cudaGetSymbolAddress((void**)&ckv, g_ckv);
    cudaGetSymbolAddress((void**)&cq,  g_cq);
    cudaGetSymbolAddress((void**)&kv,  g_kv);
    cudaGetSymbolAddress((void**)&q,   g_q);
    cudaGetSymbolAddress((void**)&ctx, g_ctx);

    cudaFuncSetAttribute(attn_kernel, cudaFuncAttributeMaxDynamicSharedMemorySize, ATTN_SMEM);

    dim3 blk(256);
    tgemm_kernel<<<dim3(L_/128, MROWS/128), blk>>>(x, w_kv_down, ckv, MROWS, L_, D_);
    tgemm_kernel<<<dim3(L_/128, MROWS/128), blk>>>(x, w_q_down,  cq,  MROWS, L_, D_);
    tgemm_kernel<<<dim3((H_*KVDIM)/128, MROWS/128), blk>>>(ckv, w_kv_up, kv, MROWS, H_*KVDIM, L_);
    tgemm_kernel<<<dim3((H_*QDIM)/128,  MROWS/128), blk>>>(cq,  w_q_up,  q,  MROWS, H_*QDIM,  L_);
    rope_kernel<<<MROWS, 512>>>();
    attn_kernel<<<dim3(S_/TQ, H_, B_), 256, ATTN_SMEM>>>();
    tgemm_kernel<<<dim3(D_/128, MROWS/128), blk>>>(ctx, w_o, out, MROWS, D_, D_);
}

// round 5
// speedup vs baseline: 2.8167x; 1.0637x over previous
#include <cuda_runtime.h>
#include <cstdint>
#include <math.h>
#include <mma.h>

using namespace nvcuda;

// Problem constants
#define B_ 2
#define S_ 2048
#define D_ 2048
#define H_ 16
#define HD_ 128
#define RD_ 64
#define L_ 512
#define QDIM (HD_ + RD_)      // 192
#define KVDIM (2*HD_ + RD_)   // 320
#define MROWS (B_ * S_)       // 4096

// Scratch (device globals; no cudaMalloc allowed)
__device__ float g_ckv[MROWS * L_];
__device__ float g_cq [MROWS * L_];
__device__ float g_kv [MROWS * H_ * KVDIM];
__device__ float g_q  [MROWS * H_ * QDIM];
__device__ float g_ctx[MROWS * H_ * HD_];

// ----------------------------------------------------------------------------
// cp.async helpers
// ----------------------------------------------------------------------------
__device__ __forceinline__ void cp16(float* dst, const float* src) {
    unsigned int s = (unsigned int)__cvta_generic_to_shared(dst);
    asm volatile("cp.async.cg.shared.global [%0], [%1], 16;\n" :: "r"(s), "l"(src));
}
#define CP_COMMIT() asm volatile("cp.async.commit_group;\n" ::: "memory")
#define CP_WAIT1()  asm volatile("cp.async.wait_group 1;\n" ::: "memory")

// ----------------------------------------------------------------------------
// TF32 tensor-core GEMM with 3-stage cp.async pipeline.
// C[M,N] = A[M,K] @ B[K,N], row-major fp32 in/out.
// 128x128 block tile, BK=32, 256 threads = 8 warps (2x4), warp tile 64x32.
// ----------------------------------------------------------------------------
#define AP 36     // A smem pitch (32 + 4)
#define BP 132    // B smem pitch (128 + 4)
#define STAGES 3
#define A_STG (128 * AP)
#define B_STG (32 * BP)
#define GEMM_SMEM (STAGES * (A_STG + B_STG) * (int)sizeof(float))

__global__ void __launch_bounds__(256) tgemm_kernel(
    const float* __restrict__ A, const float* __restrict__ Bm,
    float* __restrict__ C, int M, int N, int K)
{
    extern __shared__ float sm_g[];
    float* As = sm_g;                       // [STAGES][128*AP]
    float* Bs = sm_g + STAGES * A_STG;      // [STAGES][32*BP]

    const int tid  = threadIdx.x;
    const int bRow = blockIdx.y * 128;
    const int bCol = blockIdx.x * 128;
    const int w    = tid >> 5;
    const int wm   = w & 1;
    const int wn   = w >> 1;

    wmma::fragment<wmma::accumulator, 16, 16, 8, float> c[4][2];
#pragma unroll
    for (int i = 0; i < 4; i++)
#pragma unroll
        for (int j = 0; j < 2; j++) wmma::fill_fragment(c[i][j], 0.f);

    const int ktiles = K >> 5;

    // per-thread load coordinates
    const int ar  = tid >> 3;   // A: 8 float4 per row
    const int ac4 = tid & 7;
    const int brr = tid >> 5;   // B: 32 float4 per row
    const int bc4 = tid & 31;

    auto load_tile = [&](int buf, int kt) {
        float* as = As + buf * A_STG;
        float* bs = Bs + buf * B_STG;
        const float* Ag = A + (size_t)bRow * K + kt * 32;
        const float* Bg = Bm + (size_t)(kt * 32) * N + bCol;
#pragma unroll
        for (int p = 0; p < 4; p++) {
            int r = p * 32 + ar;
            cp16(&as[r * AP + ac4 * 4], Ag + (size_t)r * K + ac4 * 4);
            int rb = p * 8 + brr;
            cp16(&bs[rb * BP + bc4 * 4], Bg + (size_t)rb * N + bc4 * 4);
        }
    };

    load_tile(0, 0); CP_COMMIT();
    load_tile(1, 1); CP_COMMIT();

    for (int i = 0; i < ktiles; i++) {
        CP_WAIT1();
        __syncthreads();
        if (i + 2 < ktiles) load_tile((i + 2) % STAGES, i + 2);
        CP_COMMIT();

        const float* as = As + (i % STAGES) * A_STG;
        const float* bs = Bs + (i % STAGES) * B_STG;
#pragma unroll
        for (int ks = 0; ks < 32; ks += 8) {
            wmma::fragment<wmma::matrix_a, 16, 16, 8, wmma::precision::tf32, wmma::row_major> a[4];
            wmma::fragment<wmma::matrix_b, 16, 16, 8, wmma::precision::tf32, wmma::row_major> b[2];
#pragma unroll
            for (int ii = 0; ii < 4; ii++) {
                wmma::load_matrix_sync(a[ii], &as[(wm * 64 + ii * 16) * AP + ks], AP);
#pragma unroll
                for (int t = 0; t < a[ii].num_elements; t++)
                    a[ii].x[t] = wmma::__float_to_tf32(a[ii].x[t]);
            }
#pragma unroll
            for (int j = 0; j < 2; j++) {
                wmma::load_matrix_sync(b[j], &bs[ks * BP + wn * 32 + j * 16], BP);
#pragma unroll
                for (int t = 0; t < b[j].num_elements; t++)
                    b[j].x[t] = wmma::__float_to_tf32(b[j].x[t]);
            }
#pragma unroll
            for (int ii = 0; ii < 4; ii++)
#pragma unroll
                for (int j = 0; j < 2; j++)
                    wmma::mma_sync(c[ii][j], a[ii], b[j], c[ii][j]);
        }
    }

#pragma unroll
    for (int i = 0; i < 4; i++)
#pragma unroll
        for (int j = 0; j < 2; j++) {
            size_t row = bRow + wm * 64 + i * 16;
            size_t col = bCol + wn * 32 + j * 16;
            wmma::store_matrix_sync(C + row * N + col, c[i][j], N, wmma::mem_row_major);
        }
}

// ----------------------------------------------------------------------------
// RoPE (in place)
// ----------------------------------------------------------------------------
__global__ void __launch_bounds__(512) rope_kernel()
{
    const int bs  = blockIdx.x;
    const int s   = bs % S_;
    const int tid = threadIdx.x;
    const int h   = tid >> 5;
    const int i   = tid & 31;

    const float inv_freq = __expf(-(float)i * (9.210340371976184f / 32.0f));
    const float freq = (float)s * inv_freq;
    const float c  = cosf(freq);
    const float sn = sinf(freq);

    {
        size_t base = ((size_t)bs * H_ + h) * QDIM + HD_;
        float x1 = g_q[base + i];
        float x2 = g_q[base + i + 32];
        g_q[base + i]      = x1 * c - x2 * sn;
        g_q[base + i + 32] = x2 * c + x1 * sn;
    }
    {
        size_t base = ((size_t)bs * H_ + h) * KVDIM + HD_;
        float x1 = g_kv[base + i];
        float x2 = g_kv[base + i + 32];
        g_kv[base + i]      = x1 * c - x2 * sn;
        g_kv[base + i + 32] = x2 * c + x1 * sn;
    }
}

// ----------------------------------------------------------------------------
// Causal flash attention, fp32, register-tiled (unchanged).
// ----------------------------------------------------------------------------
#define TQ 64
#define TK 64
#define QP 68
#define VP 132
#define SP 68
#define ATTN_SMEM ((192*QP + 32*QP + TK*VP + TQ*SP + 192) * (int)sizeof(float))

__global__ void __launch_bounds__(256) attn_kernel()
{
    extern __shared__ float sm[];
    float* sQt  = sm;
    float* sKt  = sQt + 192 * QP;
    float* sV   = sKt + 32 * QP;
    float* sS   = sV  + TK * VP;
    float* mRow = sS  + TQ * SP;
    float* lRow = mRow + 64;
    float* aRow = lRow + 64;

    const int qt  = blockIdx.x;
    const int h   = blockIdx.y;
    const int b   = blockIdx.z;
    const int qs  = qt * TQ;
    const int tid = threadIdx.x;
    const int ty  = tid >> 4;
    const int tx  = tid & 15;
    const int r0  = ty * 4;

    for (int idx = tid; idx < TQ * QDIM; idx += 256) {
        int r = idx / QDIM, k = idx % QDIM;
        sQt[k * QP + r] = g_q[((size_t)(b * S_ + qs + r) * H_ + h) * QDIM + k];
    }
    if (tid < TQ) { mRow[tid] = -INFINITY; lRow[tid] = 0.f; }

    float acc[4][8];
#pragma unroll
    for (int i = 0; i < 4; i++)
#pragma unroll
        for (int j = 0; j < 8; j++) acc[i][j] = 0.f;

    const float scale = 0.07216878364870323f;

    for (int kt = 0; kt <= qt; kt++) {
        const int ks = kt * TK;
        __syncthreads();

        for (int idx4 = tid; idx4 < TK * (HD_ / 4); idx4 += 256) {
            int c = idx4 >> 5, j4 = idx4 & 31;
            float4 v = *(const float4*)(g_kv + ((size_t)(b * S_ + ks + c) * H_ + h) * KVDIM + QDIM + j4 * 4);
            *(float4*)&sV[c * VP + j4 * 4] = v;
        }

        float s[4][4];
#pragma unroll
        for (int i = 0; i < 4; i++)
#pragma unroll
            for (int j = 0; j < 4; j++) s[i][j] = 0.f;

        for (int dc = 0; dc < 6; dc++) {
            if (dc > 0) __syncthreads();
            {
                int c = tid >> 5;
                int d = tid & 31;
#pragma unroll
                for (int rr = 0; rr < 8; rr++) {
                    int kc = c + rr * 8;
                    sKt[d * QP + kc] = g_kv[((size_t)(b * S_ + ks + kc) * H_ + h) * KVDIM + dc * 32 + d];
                }
            }
            __syncthreads();
#pragma unroll
            for (int k = 0; k < 32; k++) {
                const int kk = dc * 32 + k;
                float4 qa = *(const float4*)&sQt[kk * QP + r0];
                float4 kb = *(const float4*)&sKt[k  * QP + tx * 4];
                float ra[4] = {qa.x, qa.y, qa.z, qa.w};
                float rb[4] = {kb.x, kb.y, kb.z, kb.w};
#pragma unroll
                for (int i = 0; i < 4; i++)
#pragma unroll
                    for (int j = 0; j < 4; j++)
                        s[i][j] += ra[i] * rb[j];
            }
        }

        {
            const bool diag = (kt == qt);
#pragma unroll
            for (int i = 0; i < 4; i++) {
                const int gr = qs + r0 + i;
                float4 w;
                float* ws = &w.x;
#pragma unroll
                for (int j = 0; j < 4; j++) {
                    int kc = ks + tx * 4 + j;
                    ws[j] = (diag && kc > gr) ? -1e30f : s[i][j] * scale;
                }
                *(float4*)&sS[(r0 + i) * SP + tx * 4] = w;
            }
        }
        __syncthreads();

        if (tid < TQ) {
            const int r = tid;
            float mold = mRow[r];
            float mx = mold;
#pragma unroll
            for (int c = 0; c < TK; c++) mx = fmaxf(mx, sS[r * SP + c]);
            float a = __expf(mold - mx);
            float sum = 0.f;
#pragma unroll
            for (int c = 0; c < TK; c++) {
                float p = __expf(sS[r * SP + c] - mx);
                sS[r * SP + c] = p;
                sum += p;
            }
            lRow[r] = lRow[r] * a + sum;
            mRow[r] = mx;
            aRow[r] = a;
        }
        __syncthreads();

        {
            float al[4];
#pragma unroll
            for (int i = 0; i < 4; i++) al[i] = aRow[r0 + i];
#pragma unroll
            for (int i = 0; i < 4; i++)
#pragma unroll
                for (int j = 0; j < 8; j++) acc[i][j] *= al[i];

#pragma unroll 4
            for (int c = 0; c < TK; c++) {
                float4 v0 = *(const float4*)&sV[c * VP + tx * 8];
                float4 v1 = *(const float4*)&sV[c * VP + tx * 8 + 4];
                float p[4];
#pragma unroll
                for (int i = 0; i < 4; i++) p[i] = sS[(r0 + i) * SP + c];
#pragma unroll
                for (int i = 0; i < 4; i++) {
                    acc[i][0] += p[i] * v0.x;
                    acc[i][1] += p[i] * v0.y;
                    acc[i][2] += p[i] * v0.z;
                    acc[i][3] += p[i] * v0.w;
                    acc[i][4] += p[i] * v1.x;
                    acc[i][5] += p[i] * v1.y;
                    acc[i][6] += p[i] * v1.z;
                    acc[i][7] += p[i] * v1.w;
                }
            }
        }
    }

#pragma unroll
    for (int i = 0; i < 4; i++) {
        const float invl = 1.0f / lRow[r0 + i];
        size_t ob = ((size_t)(b * S_ + qs + r0 + i) * H_ + h) * HD_ + tx * 8;
        float4 o0 = make_float4(acc[i][0]*invl, acc[i][1]*invl, acc[i][2]*invl, acc[i][3]*invl);
        float4 o1 = make_float4(acc[i][4]*invl, acc[i][5]*invl, acc[i][6]*invl, acc[i][7]*invl);
        *(float4*)(g_ctx + ob)     = o0;
        *(float4*)(g_ctx + ob + 4) = o1;
    }
}

// ----------------------------------------------------------------------------
// Launch
// ----------------------------------------------------------------------------
extern "C" void kernel_launch(void* const* d_in, const int* in_sizes, int n_in,
                              void* d_out, int out_size)
{
    (void)in_sizes; (void)n_in; (void)out_size;
    const float* x         = (const float*)d_in[0];
    const float* w_kv_down = (const float*)d_in[2];
    const float* w_kv_up   = (const float*)d_in[3];
    const float* w_q_down  = (const float*)d_in[4];
    const float* w_q_up    = (const float*)d_in[5];
    const float* w_o       = (const float*)d_in[6];
    float* out = (float*)d_out;

    float *ckv, *cq, *kv, *q, *ctx;
    cudaGetSymbolAddress((void**)&ckv, g_ckv);
    cudaGetSymbolAddress((void**)&cq,  g_cq);
    cudaGetSymbolAddress((void**)&kv,  g_kv);
    cudaGetSymbolAddress((void**)&q,   g_q);
    cudaGetSymbolAddress((void**)&ctx, g_ctx);

    cudaFuncSetAttribute(tgemm_kernel, cudaFuncAttributeMaxDynamicSharedMemorySize, GEMM_SMEM);
    cudaFuncSetAttribute(attn_kernel,  cudaFuncAttributeMaxDynamicSharedMemorySize, ATTN_SMEM);

    dim3 blk(256);
    tgemm_kernel<<<dim3(L_/128, MROWS/128), blk, GEMM_SMEM>>>(x, w_kv_down, ckv, MROWS, L_, D_);
    tgemm_kernel<<<dim3(L_/128, MROWS/128), blk, GEMM_SMEM>>>(x, w_q_down,  cq,  MROWS, L_, D_);
    tgemm_kernel<<<dim3((H_*KVDIM)/128, MROWS/128), blk, GEMM_SMEM>>>(ckv, w_kv_up, kv, MROWS, H_*KVDIM, L_);
    tgemm_kernel<<<dim3((H_*QDIM)/128,  MROWS/128), blk, GEMM_SMEM>>>(cq,  w_q_up,  q,  MROWS, H_*QDIM,  L_);
    rope_kernel<<<MROWS, 512>>>();
    attn_kernel<<<dim3(S_/TQ, H_, B_), 256, ATTN_SMEM>>>();
    tgemm_kernel<<<dim3(D_/128, MROWS/128), blk, GEMM_SMEM>>>(ctx, w_o, out, MROWS, D_, D_);
}

// round 6
// speedup vs baseline: 2.9688x; 1.0540x over previous
#include <cuda_runtime.h>
#include <cstdint>
#include <math.h>
#include <mma.h>

using namespace nvcuda;

// Problem constants
#define B_ 2
#define S_ 2048
#define D_ 2048
#define H_ 16
#define HD_ 128
#define RD_ 64
#define L_ 512
#define QDIM (HD_ + RD_)      // 192
#define KVDIM (2*HD_ + RD_)   // 320
#define MROWS (B_ * S_)       // 4096

// Scratch (device globals; no cudaMalloc allowed)
__device__ float g_ckv[MROWS * L_];
__device__ float g_cq [MROWS * L_];
__device__ float g_kv [MROWS * H_ * KVDIM];
__device__ float g_q  [MROWS * H_ * QDIM];
__device__ float g_ctx[MROWS * H_ * HD_];
// tf32-rounded operand copies
__device__ float g_xt [MROWS * D_];
__device__ float g_w1t[D_ * L_];            // w_kv_down
__device__ float g_w2t[L_ * H_ * KVDIM];    // w_kv_up
__device__ float g_w3t[D_ * L_];            // w_q_down
__device__ float g_w4t[L_ * H_ * QDIM];     // w_q_up
__device__ float g_w5t[H_ * HD_ * D_];      // w_o

// ----------------------------------------------------------------------------
// Elementwise fp32 -> tf32-valued fp32 (RN), vectorized
// ----------------------------------------------------------------------------
__global__ void __launch_bounds__(256) cvt_tf32_kernel(
    const float4* __restrict__ in, float4* __restrict__ out, int n4)
{
    int i = blockIdx.x * blockDim.x + threadIdx.x;
    if (i < n4) {
        float4 v = in[i];
        v.x = wmma::__float_to_tf32(v.x);
        v.y = wmma::__float_to_tf32(v.y);
        v.z = wmma::__float_to_tf32(v.z);
        v.w = wmma::__float_to_tf32(v.w);
        out[i] = v;
    }
}

// ----------------------------------------------------------------------------
// cp.async helpers
// ----------------------------------------------------------------------------
__device__ __forceinline__ void cp16(float* dst, const float* src) {
    unsigned int s = (unsigned int)__cvta_generic_to_shared(dst);
    asm volatile("cp.async.cg.shared.global [%0], [%1], 16;\n" :: "r"(s), "l"(src));
}
#define CP_COMMIT() asm volatile("cp.async.commit_group;\n" ::: "memory")
#define CP_WAIT1()  asm volatile("cp.async.wait_group 1;\n" ::: "memory")

// ----------------------------------------------------------------------------
// TF32 tensor-core GEMM, 3-stage cp.async pipeline, operands pre-rounded.
// C[M,N] = A[M,K] @ B[K,N], row-major. roundC: round output to tf32 (RN).
// 128x128 block tile, BK=32, 256 threads = 8 warps (2x4), warp tile 64x32.
// ----------------------------------------------------------------------------
#define AP 36
#define BP 132
#define STAGES 3
#define A_STG (128 * AP)
#define B_STG (32 * BP)
#define GEMM_SMEM (STAGES * (A_STG + B_STG) * (int)sizeof(float))

__global__ void __launch_bounds__(256, 2) tgemm_kernel(
    const float* __restrict__ A, const float* __restrict__ Bm,
    float* __restrict__ C, int M, int N, int K, int roundC)
{
    extern __shared__ float sm_g[];
    float* As = sm_g;
    float* Bs = sm_g + STAGES * A_STG;

    const int tid  = threadIdx.x;
    const int bRow = blockIdx.y * 128;
    const int bCol = blockIdx.x * 128;
    const int w    = tid >> 5;
    const int wm   = w & 1;
    const int wn   = w >> 1;

    wmma::fragment<wmma::accumulator, 16, 16, 8, float> c[4][2];
#pragma unroll
    for (int i = 0; i < 4; i++)
#pragma unroll
        for (int j = 0; j < 2; j++) wmma::fill_fragment(c[i][j], 0.f);

    const int ktiles = K >> 5;

    const int ar  = tid >> 3;
    const int ac4 = tid & 7;
    const int brr = tid >> 5;
    const int bc4 = tid & 31;

    auto load_tile = [&](int buf, int kt) {
        float* as = As + buf * A_STG;
        float* bs = Bs + buf * B_STG;
        const float* Ag = A + (size_t)bRow * K + kt * 32;
        const float* Bg = Bm + (size_t)(kt * 32) * N + bCol;
#pragma unroll
        for (int p = 0; p < 4; p++) {
            int r = p * 32 + ar;
            cp16(&as[r * AP + ac4 * 4], Ag + (size_t)r * K + ac4 * 4);
            int rb = p * 8 + brr;
            cp16(&bs[rb * BP + bc4 * 4], Bg + (size_t)rb * N + bc4 * 4);
        }
    };

    load_tile(0, 0); CP_COMMIT();
    load_tile(1, 1); CP_COMMIT();

    for (int i = 0; i < ktiles; i++) {
        CP_WAIT1();
        __syncthreads();
        if (i + 2 < ktiles) load_tile((i + 2) % STAGES, i + 2);
        CP_COMMIT();

        const float* as = As + (i % STAGES) * A_STG;
        const float* bs = Bs + (i % STAGES) * B_STG;
#pragma unroll
        for (int ks = 0; ks < 32; ks += 8) {
            wmma::fragment<wmma::matrix_a, 16, 16, 8, wmma::precision::tf32, wmma::row_major> a[4];
            wmma::fragment<wmma::matrix_b, 16, 16, 8, wmma::precision::tf32, wmma::row_major> b[2];
#pragma unroll
            for (int ii = 0; ii < 4; ii++)
                wmma::load_matrix_sync(a[ii], &as[(wm * 64 + ii * 16) * AP + ks], AP);
#pragma unroll
            for (int j = 0; j < 2; j++)
                wmma::load_matrix_sync(b[j], &bs[ks * BP + wn * 32 + j * 16], BP);
#pragma unroll
            for (int ii = 0; ii < 4; ii++)
#pragma unroll
                for (int j = 0; j < 2; j++)
                    wmma::mma_sync(c[ii][j], a[ii], b[j], c[ii][j]);
        }
    }

    if (roundC) {
#pragma unroll
        for (int i = 0; i < 4; i++)
#pragma unroll
            for (int j = 0; j < 2; j++)
#pragma unroll
                for (int t = 0; t < c[i][j].num_elements; t++)
                    c[i][j].x[t] = wmma::__float_to_tf32(c[i][j].x[t]);
    }

#pragma unroll
    for (int i = 0; i < 4; i++)
#pragma unroll
        for (int j = 0; j < 2; j++) {
            size_t row = bRow + wm * 64 + i * 16;
            size_t col = bCol + wn * 32 + j * 16;
            wmma::store_matrix_sync(C + row * N + col, c[i][j], N, wmma::mem_row_major);
        }
}

// ----------------------------------------------------------------------------
// RoPE (in place)
// ----------------------------------------------------------------------------
__global__ void __launch_bounds__(512) rope_kernel()
{
    const int bs  = blockIdx.x;
    const int s   = bs % S_;
    const int tid = threadIdx.x;
    const int h   = tid >> 5;
    const int i   = tid & 31;

    const float inv_freq = __expf(-(float)i * (9.210340371976184f / 32.0f));
    const float freq = (float)s * inv_freq;
    const float c  = cosf(freq);
    const float sn = sinf(freq);

    {
        size_t base = ((size_t)bs * H_ + h) * QDIM + HD_;
        float x1 = g_q[base + i];
        float x2 = g_q[base + i + 32];
        g_q[base + i]      = x1 * c - x2 * sn;
        g_q[base + i + 32] = x2 * c + x1 * sn;
    }
    {
        size_t base = ((size_t)bs * H_ + h) * KVDIM + HD_;
        float x1 = g_kv[base + i];
        float x2 = g_kv[base + i + 32];
        g_kv[base + i]      = x1 * c - x2 * sn;
        g_kv[base + i + 32] = x2 * c + x1 * sn;
    }
}

// ----------------------------------------------------------------------------
// Causal flash attention, fp32, register-tiled.
// ctx output rounded to tf32 (feeds the tf32 output GEMM).
// ----------------------------------------------------------------------------
#define TQ 64
#define TK 64
#define QP 68
#define VP 132
#define SP 68
#define ATTN_SMEM ((192*QP + 32*QP + TK*VP + TQ*SP + 192) * (int)sizeof(float))

__global__ void __launch_bounds__(256) attn_kernel()
{
    extern __shared__ float sm[];
    float* sQt  = sm;
    float* sKt  = sQt + 192 * QP;
    float* sV   = sKt + 32 * QP;
    float* sS   = sV  + TK * VP;
    float* mRow = sS  + TQ * SP;
    float* lRow = mRow + 64;
    float* aRow = lRow + 64;

    const int qt  = blockIdx.x;
    const int h   = blockIdx.y;
    const int b   = blockIdx.z;
    const int qs  = qt * TQ;
    const int tid = threadIdx.x;
    const int ty  = tid >> 4;
    const int tx  = tid & 15;
    const int r0  = ty * 4;

    for (int idx = tid; idx < TQ * QDIM; idx += 256) {
        int r = idx / QDIM, k = idx % QDIM;
        sQt[k * QP + r] = g_q[((size_t)(b * S_ + qs + r) * H_ + h) * QDIM + k];
    }
    if (tid < TQ) { mRow[tid] = -INFINITY; lRow[tid] = 0.f; }

    float acc[4][8];
#pragma unroll
    for (int i = 0; i < 4; i++)
#pragma unroll
        for (int j = 0; j < 8; j++) acc[i][j] = 0.f;

    const float scale = 0.07216878364870323f;

    for (int kt = 0; kt <= qt; kt++) {
        const int ks = kt * TK;
        __syncthreads();

        for (int idx4 = tid; idx4 < TK * (HD_ / 4); idx4 += 256) {
            int c = idx4 >> 5, j4 = idx4 & 31;
            float4 v = *(const float4*)(g_kv + ((size_t)(b * S_ + ks + c) * H_ + h) * KVDIM + QDIM + j4 * 4);
            *(float4*)&sV[c * VP + j4 * 4] = v;
        }

        float s[4][4];
#pragma unroll
        for (int i = 0; i < 4; i++)
#pragma unroll
            for (int j = 0; j < 4; j++) s[i][j] = 0.f;

        for (int dc = 0; dc < 6; dc++) {
            if (dc > 0) __syncthreads();
            {
                int c = tid >> 5;
                int d = tid & 31;
#pragma unroll
                for (int rr = 0; rr < 8; rr++) {
                    int kc = c + rr * 8;
                    sKt[d * QP + kc] = g_kv[((size_t)(b * S_ + ks + kc) * H_ + h) * KVDIM + dc * 32 + d];
                }
            }
            __syncthreads();
#pragma unroll
            for (int k = 0; k < 32; k++) {
                const int kk = dc * 32 + k;
                float4 qa = *(const float4*)&sQt[kk * QP + r0];
                float4 kb = *(const float4*)&sKt[k  * QP + tx * 4];
                float ra[4] = {qa.x, qa.y, qa.z, qa.w};
                float rb[4] = {kb.x, kb.y, kb.z, kb.w};
#pragma unroll
                for (int i = 0; i < 4; i++)
#pragma unroll
                    for (int j = 0; j < 4; j++)
                        s[i][j] += ra[i] * rb[j];
            }
        }

        {
            const bool diag = (kt == qt);
#pragma unroll
            for (int i = 0; i < 4; i++) {
                const int gr = qs + r0 + i;
                float4 w;
                float* ws = &w.x;
#pragma unroll
                for (int j = 0; j < 4; j++) {
                    int kc = ks + tx * 4 + j;
                    ws[j] = (diag && kc > gr) ? -1e30f : s[i][j] * scale;
                }
                *(float4*)&sS[(r0 + i) * SP + tx * 4] = w;
            }
        }
        __syncthreads();

        if (tid < TQ) {
            const int r = tid;
            float mold = mRow[r];
            float mx = mold;
#pragma unroll
            for (int c = 0; c < TK; c++) mx = fmaxf(mx, sS[r * SP + c]);
            float a = __expf(mold - mx);
            float sum = 0.f;
#pragma unroll
            for (int c = 0; c < TK; c++) {
                float p = __expf(sS[r * SP + c] - mx);
                sS[r * SP + c] = p;
                sum += p;
            }
            lRow[r] = lRow[r] * a + sum;
            mRow[r] = mx;
            aRow[r] = a;
        }
        __syncthreads();

        {
            float al[4];
#pragma unroll
            for (int i = 0; i < 4; i++) al[i] = aRow[r0 + i];
#pragma unroll
            for (int i = 0; i < 4; i++)
#pragma unroll
                for (int j = 0; j < 8; j++) acc[i][j] *= al[i];

#pragma unroll 4
            for (int c = 0; c < TK; c++) {
                float4 v0 = *(const float4*)&sV[c * VP + tx * 8];
                float4 v1 = *(const float4*)&sV[c * VP + tx * 8 + 4];
                float p[4];
#pragma unroll
                for (int i = 0; i < 4; i++) p[i] = sS[(r0 + i) * SP + c];
#pragma unroll
                for (int i = 0; i < 4; i++) {
                    acc[i][0] += p[i] * v0.x;
                    acc[i][1] += p[i] * v0.y;
                    acc[i][2] += p[i] * v0.z;
                    acc[i][3] += p[i] * v0.w;
                    acc[i][4] += p[i] * v1.x;
                    acc[i][5] += p[i] * v1.y;
                    acc[i][6] += p[i] * v1.z;
                    acc[i][7] += p[i] * v1.w;
                }
            }
        }
    }

#pragma unroll
    for (int i = 0; i < 4; i++) {
        const float invl = 1.0f / lRow[r0 + i];
        size_t ob = ((size_t)(b * S_ + qs + r0 + i) * H_ + h) * HD_ + tx * 8;
        float o[8];
#pragma unroll
        for (int j = 0; j < 8; j++) o[j] = wmma::__float_to_tf32(acc[i][j] * invl);
        *(float4*)(g_ctx + ob)     = make_float4(o[0], o[1], o[2], o[3]);
        *(float4*)(g_ctx + ob + 4) = make_float4(o[4], o[5], o[6], o[7]);
    }
}

// ----------------------------------------------------------------------------
// Launch
// ----------------------------------------------------------------------------
extern "C" void kernel_launch(void* const* d_in, const int* in_sizes, int n_in,
                              void* d_out, int out_size)
{
    (void)in_sizes; (void)n_in; (void)out_size;
    const float* x         = (const float*)d_in[0];
    const float* w_kv_down = (const float*)d_in[2];
    const float* w_kv_up   = (const float*)d_in[3];
    const float* w_q_down  = (const float*)d_in[4];
    const float* w_q_up    = (const float*)d_in[5];
    const float* w_o       = (const float*)d_in[6];
    float* out = (float*)d_out;

    float *ckv, *cq, *kv, *q, *ctx, *xt, *w1t, *w2t, *w3t, *w4t, *w5t;
    cudaGetSymbolAddress((void**)&ckv, g_ckv);
    cudaGetSymbolAddress((void**)&cq,  g_cq);
    cudaGetSymbolAddress((void**)&kv,  g_kv);
    cudaGetSymbolAddress((void**)&q,   g_q);
    cudaGetSymbolAddress((void**)&ctx, g_ctx);
    cudaGetSymbolAddress((void**)&xt,  g_xt);
    cudaGetSymbolAddress((void**)&w1t, g_w1t);
    cudaGetSymbolAddress((void**)&w2t, g_w2t);
    cudaGetSymbolAddress((void**)&w3t, g_w3t);
    cudaGetSymbolAddress((void**)&w4t, g_w4t);
    cudaGetSymbolAddress((void**)&w5t, g_w5t);

    cudaFuncSetAttribute(tgemm_kernel, cudaFuncAttributeMaxDynamicSharedMemorySize, GEMM_SMEM);
    cudaFuncSetAttribute(attn_kernel,  cudaFuncAttributeMaxDynamicSharedMemorySize, ATTN_SMEM);

    auto cvt = [&](const float* src, float* dst, int n) {
        int n4 = n >> 2;
        cvt_tf32_kernel<<<(n4 + 255) / 256, 256>>>((const float4*)src, (float4*)dst, n4);
    };

    cvt(x,         xt,  MROWS * D_);
    cvt(w_kv_down, w1t, D_ * L_);
    cvt(w_kv_up,   w2t, L_ * H_ * KVDIM);
    cvt(w_q_down,  w3t, D_ * L_);
    cvt(w_q_up,    w4t, L_ * H_ * QDIM);
    cvt(w_o,       w5t, H_ * HD_ * D_);

    dim3 blk(256);
    tgemm_kernel<<<dim3(L_/128, MROWS/128), blk, GEMM_SMEM>>>(xt, w1t, ckv, MROWS, L_, D_, 1);
    tgemm_kernel<<<dim3(L_/128, MROWS/128), blk, GEMM_SMEM>>>(xt, w3t, cq,  MROWS, L_, D_, 1);
    tgemm_kernel<<<dim3((H_*KVDIM)/128, MROWS/128), blk, GEMM_SMEM>>>(ckv, w2t, kv, MROWS, H_*KVDIM, L_, 0);
    tgemm_kernel<<<dim3((H_*QDIM)/128,  MROWS/128), blk, GEMM_SMEM>>>(cq,  w4t, q,  MROWS, H_*QDIM,  L_, 0);
    rope_kernel<<<MROWS, 512>>>();
    attn_kernel<<<dim3(S_/TQ, H_, B_), 256, ATTN_SMEM>>>();
    tgemm_kernel<<<dim3(D_/128, MROWS/128), blk, GEMM_SMEM>>>(ctx, w5t, out, MROWS, D_, D_, 0);
}